// round 16
// baseline (speedup 1.0000x reference)
#include <cuda_runtime.h>
#include <cuda_fp16.h>
#include <cstdint>

#define D_MODEL 2048
#define D_STATE 16
#define D_INNER 4096
#define BATCH   2048
#define LN_EPS  1e-5f
#define HALF_B  (BATCH / 2)

// ---------------- scratch (device globals: allocation-free) ----------------
__device__ float g_xz [(size_t)BATCH * 2 * D_INNER];          // 64 MB (x_main | z)
__device__ float g_A  [D_INNER * D_STATE];
__device__ float g_bcd[(size_t)BATCH * 33];                   // B(16) C(16) delta_raw(1)
__device__ __half g_xh [(size_t)BATCH * D_MODEL];             // xn, fp16
__device__ __half g_wi [(size_t)2 * D_INNER * D_MODEL];       // W_in fp16
__device__ __half g_wo [(size_t)D_MODEL * D_INNER];           // W_out fp16
__device__ __half g_yg [(size_t)BATCH * D_INNER];             // y_gated, fp16

// ---------------- helpers ----------------
__device__ __forceinline__ uint32_t smem_u32(const void* p) {
    uint32_t a;
    asm("{ .reg .u64 t; cvta.to.shared.u64 t, %1; cvt.u32.u64 %0, t; }" : "=r"(a) : "l"(p));
    return a;
}
__device__ __forceinline__ void ldsm4(uint32_t (&r)[4], uint32_t addr) {
    asm volatile("ldmatrix.sync.aligned.m8n8.x4.shared.b16 {%0,%1,%2,%3}, [%4];"
        : "=r"(r[0]), "=r"(r[1]), "=r"(r[2]), "=r"(r[3]) : "r"(addr));
}
__device__ __forceinline__ void mma16816(float (&c)[4], const uint32_t (&a)[4],
                                         uint32_t b0, uint32_t b1) {
    asm volatile("mma.sync.aligned.m16n8k16.row.col.f32.f16.f16.f32 "
        "{%0,%1,%2,%3}, {%4,%5,%6,%7}, {%8,%9}, {%0,%1,%2,%3};"
        : "+f"(c[0]), "+f"(c[1]), "+f"(c[2]), "+f"(c[3])
        : "r"(a[0]), "r"(a[1]), "r"(a[2]), "r"(a[3]), "r"(b0), "r"(b1));
}

// ---------------- small kernels ----------------
__global__ void expA_kernel(const float* __restrict__ log_A) {
    int i = blockIdx.x * 256 + threadIdx.x;
    if (i < D_INNER * D_STATE) g_A[i] = expf(log_A[i]);
}

// fp32 -> fp16 convert (weights)
__global__ __launch_bounds__(256) void cvt_kernel(const float* __restrict__ s,
                                                  __half* __restrict__ o, int n4) {
    int i = blockIdx.x * 256 + threadIdx.x;
    if (i >= n4) return;
    float4 v = ((const float4*)s)[i];
    __half2 a, b;
    a.x = __float2half(v.x); a.y = __float2half(v.y);
    b.x = __float2half(v.z); b.y = __float2half(v.w);
    *(__half2*)(o + (size_t)i * 4)     = a;
    *(__half2*)(o + (size_t)i * 4 + 2) = b;
}

// LayerNorm -> single fp16 xn
__global__ __launch_bounds__(256) void ln_kernel(const float* __restrict__ x,
                                                 const float* __restrict__ gamma,
                                                 const float* __restrict__ beta) {
    int b = blockIdx.x, tid = threadIdx.x;
    const float4* xr = (const float4*)(x + (size_t)b * D_MODEL);
    float4 v0 = xr[tid];
    float4 v1 = xr[tid + 256];
    float s = v0.x + v0.y + v0.z + v0.w + v1.x + v1.y + v1.z + v1.w;
    float q = v0.x*v0.x + v0.y*v0.y + v0.z*v0.z + v0.w*v0.w
            + v1.x*v1.x + v1.y*v1.y + v1.z*v1.z + v1.w*v1.w;
    #pragma unroll
    for (int o = 16; o; o >>= 1) {
        s += __shfl_xor_sync(0xffffffffu, s, o);
        q += __shfl_xor_sync(0xffffffffu, q, o);
    }
    __shared__ float rs[8], rq[8];
    int w = tid >> 5, l = tid & 31;
    if (l == 0) { rs[w] = s; rq[w] = q; }
    __syncthreads();
    s = rs[0]+rs[1]+rs[2]+rs[3]+rs[4]+rs[5]+rs[6]+rs[7];
    q = rq[0]+rq[1]+rq[2]+rq[3]+rq[4]+rq[5]+rq[6]+rq[7];
    float mean = s * (1.0f / D_MODEL);
    float var  = q * (1.0f / D_MODEL) - mean * mean;
    float rstd = rsqrtf(var + LN_EPS);
    const float4* gr = (const float4*)gamma;
    const float4* br = (const float4*)beta;
    float4 g0 = gr[tid], g1 = gr[tid + 256];
    float4 b0 = br[tid], b1 = br[tid + 256];
    size_t base = (size_t)b * D_MODEL;
    __half2 p0, p1, p2, p3;
    p0.x = __float2half((v0.x-mean)*rstd*g0.x + b0.x);
    p0.y = __float2half((v0.y-mean)*rstd*g0.y + b0.y);
    p1.x = __float2half((v0.z-mean)*rstd*g0.z + b0.z);
    p1.y = __float2half((v0.w-mean)*rstd*g0.w + b0.w);
    p2.x = __float2half((v1.x-mean)*rstd*g1.x + b1.x);
    p2.y = __float2half((v1.y-mean)*rstd*g1.y + b1.y);
    p3.x = __float2half((v1.z-mean)*rstd*g1.z + b1.z);
    p3.y = __float2half((v1.w-mean)*rstd*g1.w + b1.w);
    *(__half2*)(g_xh + base + tid*4)          = p0;
    *(__half2*)(g_xh + base + tid*4 + 2)      = p1;
    *(__half2*)(g_xh + base + 1024 + tid*4)   = p2;
    *(__half2*)(g_xh + base + 1024 + tid*4+2) = p3;
}

// ---------------- mma.sync fp16 NT GEMM, 64x64 warp tiles ----------------
// C[M,N] = A[M,K]*B[N,K]^T (+R).  CTA: 128x128, BK=32, 4 warps (2x2),
// warp tile 64x64. 4-stage cp.async pipeline, 2 CTAs/SM. m0 = row offset.
#define GBK        32
#define ROW_B      80                                  // padded row bytes (40 elems)
#define MAT_BYTES  (128 * ROW_B)                       // 10240
#define STG_BYTES  (2 * MAT_BYTES)                     // 20480 (A|B)
#define NSTAGE     4
#define GEMM_SMEM  (NSTAGE * STG_BYTES)                // 81920

__device__ __forceinline__ void ld_mat32(uint32_t dst, const __half* __restrict__ G,
                                         int rb, int k0, int K, int tid) {
    #pragma unroll
    for (int i = 0; i < 4; i++) {
        int c = tid + i * 128;                 // 0..511
        int row = c >> 2, kc = c & 3;
        uint32_t d = dst + (uint32_t)(row * ROW_B + kc * 16);
        const __half* s = G + (size_t)(rb + row) * K + k0 + kc * 8;
        asm volatile("cp.async.cg.shared.global [%0], [%1], 16;\n" :: "r"(d), "l"(s) : "memory");
    }
}

__global__ __launch_bounds__(128, 2) void gemm_mma_kernel(
    const __half* __restrict__ A, const __half* __restrict__ B,
    float* __restrict__ C, const float* __restrict__ Rp, int M, int N, int K, int m0)
{
    extern __shared__ char smem_raw[];
    uint32_t sbase = smem_u32(smem_raw);
    const int tid = threadIdx.x, wid = tid >> 5, lane = tid & 31;
    const int bm = m0 + blockIdx.y * 128, bn = blockIdx.x * 128;
    const int warp_m = (wid >> 1) * 64;        // 0 or 64
    const int warp_n = (wid & 1) * 64;         // 0 or 64
    const int NCH = K / GBK;

    float acc[4][8][4];
    #pragma unroll
    for (int i = 0; i < 4; i++)
        #pragma unroll
        for (int n = 0; n < 8; n++)
            #pragma unroll
            for (int e = 0; e < 4; e++) acc[i][n][e] = 0.0f;

    // lane-dependent ldmatrix address components
    const int arow = lane & 15;                         // A: rows m0..m0+15
    const int acol = (lane >> 4) << 3;                  // A: k-half select
    const int brow = ((lane >> 4) << 3) + (lane & 7);   // B: n within 16
    const int bcol = ((lane >> 3) & 1) << 3;            // B: k-half select

    // prologue: stages 0..2 = chunks 0..2
    #pragma unroll
    for (int p = 0; p < 3; p++) {
        uint32_t sb = sbase + p * STG_BYTES;
        ld_mat32(sb,             A, bm, p * GBK, K, tid);
        ld_mat32(sb + MAT_BYTES, B, bn, p * GBK, K, tid);
        asm volatile("cp.async.commit_group;\n" ::: "memory");
    }

    for (int j = 0; j < NCH; j++) {
        asm volatile("cp.async.wait_group 2;\n" ::: "memory");
        __syncthreads();

        // prefetch chunk j+3 into stage (j+3)%4 == (j-1)%4 (consumed last iter)
        if (j + 3 < NCH) {
            uint32_t sb = sbase + ((j + 3) % NSTAGE) * STG_BYTES;
            int k0 = (j + 3) * GBK;
            ld_mat32(sb,             A, bm, k0, K, tid);
            ld_mat32(sb + MAT_BYTES, B, bn, k0, K, tid);
        }
        asm volatile("cp.async.commit_group;\n" ::: "memory");

        uint32_t sb = sbase + (j % NSTAGE) * STG_BYTES;
        #pragma unroll
        for (int ks = 0; ks < 2; ks++) {
            const int k0 = ks * 16;
            uint32_t af[4][4], bf[4][4];
            #pragma unroll
            for (int i = 0; i < 4; i++) {
                uint32_t off = (uint32_t)((warp_m + i * 16 + arow) * ROW_B + (k0 + acol) * 2);
                ldsm4(af[i], sb + off);
            }
            #pragma unroll
            for (int jn = 0; jn < 4; jn++) {
                uint32_t off = (uint32_t)((warp_n + jn * 16 + brow) * ROW_B + (k0 + bcol) * 2);
                ldsm4(bf[jn], sb + MAT_BYTES + off);
            }
            #pragma unroll
            for (int i = 0; i < 4; i++) {
                #pragma unroll
                for (int n = 0; n < 8; n++) {
                    mma16816(acc[i][n], af[i],
                             bf[n >> 1][(n & 1) * 2], bf[n >> 1][(n & 1) * 2 + 1]);
                }
            }
        }
    }

    // epilogue: thread holds rows r0, r0+8; cols 2*(lane%4)
    #pragma unroll
    for (int i = 0; i < 4; i++) {
        int r0 = bm + warp_m + i * 16 + (lane >> 2);
        #pragma unroll
        for (int n = 0; n < 8; n++) {
            int col = bn + warp_n + n * 8 + (lane & 3) * 2;
            float2 u0 = make_float2(acc[i][n][0], acc[i][n][1]);
            float2 u1 = make_float2(acc[i][n][2], acc[i][n][3]);
            size_t o0 = (size_t)r0 * N + col;
            size_t o1 = (size_t)(r0 + 8) * N + col;
            if (Rp) {
                float2 q0 = *(const float2*)(Rp + o0);
                float2 q1 = *(const float2*)(Rp + o1);
                u0.x += q0.x; u0.y += q0.y; u1.x += q1.x; u1.y += q1.y;
            }
            *(float2*)(C + o0) = u0;
            *(float2*)(C + o1) = u1;
        }
    }
}

// ---------------- xp: [B,33] = x_main @ W_xp^T, 16 rows/block ----------------
__global__ __launch_bounds__(256) void xp_kernel(const float* __restrict__ W_xp, int b_base) {
    __shared__ float sx[16][128];
    __shared__ float sw[33][128];
    int tid = threadIdx.x, w = tid >> 5, lid = tid & 31;
    int b0 = b_base + blockIdx.x * 16;
    float acc[5][16];
    #pragma unroll
    for (int jj = 0; jj < 5; jj++)
        #pragma unroll
        for (int r = 0; r < 16; r++) acc[jj][r] = 0.0f;

    for (int kc = 0; kc < D_INNER; kc += 128) {
        {   // load 16 x 128 x_main block (512 float4)
            #pragma unroll
            for (int i = 0; i < 2; i++) {
                int idx = i * 256 + tid;           // < 512
                int r = idx >> 5, c = (idx & 31) << 2;
                *(float4*)&sx[r][c] =
                    *(const float4*)(g_xz + (size_t)(b0 + r) * (2 * D_INNER) + kc + c);
            }
        }
        {   // load 33 x 128 W_xp block (1056 float4)
            #pragma unroll
            for (int i = 0; i < 5; i++) {
                int idx = i * 256 + tid;
                if (idx < 33 * 32) {
                    int r = idx >> 5, c = (idx & 31) << 2;
                    *(float4*)&sw[r][c] = *(const float4*)(W_xp + (size_t)r * D_INNER + kc + c);
                }
            }
        }
        __syncthreads();
        #pragma unroll
        for (int jj = 0; jj < 5; jj++) {
            int j = w + jj * 8;
            if (j < 33) {
                #pragma unroll
                for (int kk = 0; kk < 4; kk++) {
                    float wv = sw[j][kk * 32 + lid];
                    #pragma unroll
                    for (int r = 0; r < 16; r++)
                        acc[jj][r] = fmaf(sx[r][kk * 32 + lid], wv, acc[jj][r]);
                }
            }
        }
        __syncthreads();
    }
    #pragma unroll
    for (int jj = 0; jj < 5; jj++) {
        int j = w + jj * 8;
        #pragma unroll
        for (int r = 0; r < 16; r++) {
            float a = acc[jj][r];
            #pragma unroll
            for (int o = 16; o; o >>= 1) a += __shfl_xor_sync(0xffffffffu, a, o);
            if (lid == 0 && j < 33) g_bcd[(size_t)(b0 + r) * 33 + j] = a;
        }
    }
}

// ---------------- elementwise SSM: 4 lanes per channel, coalesced h ---------
__global__ __launch_bounds__(256) void ssm2_kernel(const float* __restrict__ h,
                                                   const float* __restrict__ dt_bias,
                                                   const float* __restrict__ Dp,
                                                   float* __restrict__ h_new, int b_base) {
    int blk = blockIdx.x;
    int b = b_base + (blk >> 6);                   // row (64 chunks of 64 channels)
    int chunk = blk & 63;
    int tid = threadIdx.x;
    int d = chunk * 64 + (tid >> 2);               // channel
    int q = tid & 3;                               // quarter of D_STATE

    __shared__ float s_bc[33];
    if (tid < 33) s_bc[tid] = g_bcd[(size_t)b * 33 + tid];
    __syncthreads();

    float xm = g_xz[(size_t)b * (2 * D_INNER) + d];
    float t = s_bc[32] + dt_bias[d];
    float dlt = (t > 20.0f) ? t : log1pf(__expf(t));

    size_t off = ((size_t)b * D_INNER + d) * D_STATE + q * 4;
    float4 hv = __ldcs((const float4*)(h + off));
    float4 av = *(const float4*)(g_A + d * D_STATE + q * 4);
    float4 o;
    o.x = __expf(-dlt * av.x) * hv.x + dlt * s_bc[4*q + 0] * xm;
    o.y = __expf(-dlt * av.y) * hv.y + dlt * s_bc[4*q + 1] * xm;
    o.z = __expf(-dlt * av.z) * hv.z + dlt * s_bc[4*q + 2] * xm;
    o.w = __expf(-dlt * av.w) * hv.w + dlt * s_bc[4*q + 3] * xm;
    __stcs((float4*)(h_new + off), o);

    float acc = o.x * s_bc[16 + 4*q + 0] + o.y * s_bc[16 + 4*q + 1]
              + o.z * s_bc[16 + 4*q + 2] + o.w * s_bc[16 + 4*q + 3];
    acc += __shfl_xor_sync(0xffffffffu, acc, 1);
    acc += __shfl_xor_sync(0xffffffffu, acc, 2);

    if (q == 0) {
        float z = g_xz[(size_t)b * (2 * D_INNER) + D_INNER + d];
        float y = acc + Dp[d] * xm;
        float sig = 1.0f / (1.0f + __expf(-z));
        g_yg[(size_t)b * D_INNER + d] = __float2half(y * z * sig);
    }
}

// ---------------- launch: 2-stream batch-halved pipeline --------------------
extern "C" void kernel_launch(void* const* d_in, const int* in_sizes, int n_in,
                              void* d_out, int out_size) {
    const float* x     = (const float*)d_in[0];
    const float* h     = (const float*)d_in[1];
    const float* W_in  = (const float*)d_in[2];
    const float* W_xp  = (const float*)d_in[3];
    const float* log_A = (const float*)d_in[4];
    const float* dt_b  = (const float*)d_in[5];
    const float* Dp    = (const float*)d_in[6];
    const float* W_out = (const float*)d_in[7];
    const float* gamma = (const float*)d_in[8];
    const float* beta  = (const float*)d_in[9];

    float* y_out = (float*)d_out;                         // [2048, 2048]
    float* h_out = y_out + (size_t)BATCH * D_MODEL;       // [2048, 4096, 16]

    void* p;
    cudaGetSymbolAddress(&p, g_xz);  float* xz = (float*)p;
    cudaGetSymbolAddress(&p, g_xh);  __half* xh = (__half*)p;
    cudaGetSymbolAddress(&p, g_wi);  __half* wi = (__half*)p;
    cudaGetSymbolAddress(&p, g_wo);  __half* wo = (__half*)p;
    cudaGetSymbolAddress(&p, g_yg);  __half* yg = (__half*)p;

    cudaFuncSetAttribute(gemm_mma_kernel, cudaFuncAttributeMaxDynamicSharedMemorySize, GEMM_SMEM);

    // side stream + events (created per call; kernel_launch runs only twice)
    cudaStream_t s2;
    cudaStreamCreateWithFlags(&s2, cudaStreamNonBlocking);
    cudaEvent_t eFork, eCvtWi, eG1a, eG1b, eSsmA, eSsmB;
    cudaEventCreateWithFlags(&eFork,  cudaEventDisableTiming);
    cudaEventCreateWithFlags(&eCvtWi, cudaEventDisableTiming);
    cudaEventCreateWithFlags(&eG1a,   cudaEventDisableTiming);
    cudaEventCreateWithFlags(&eG1b,   cudaEventDisableTiming);
    cudaEventCreateWithFlags(&eSsmA,  cudaEventDisableTiming);
    cudaEventCreateWithFlags(&eSsmB,  cudaEventDisableTiming);

    const int n4_wi = (2 * D_INNER * D_MODEL) / 4;
    const int n4_wo = (D_MODEL * D_INNER) / 4;

    // fork s2 off the main (default) stream
    cudaEventRecord(eFork, 0);
    cudaStreamWaitEvent(s2, eFork, 0);

    // s2: W_in convert (needed by GEMM1)
    cvt_kernel<<<(n4_wi + 255) / 256, 256, 0, s2>>>(W_in, wi, n4_wi);
    cudaEventRecord(eCvtWi, s2);

    // main: LayerNorm (parallel with cvt_wi)
    ln_kernel<<<BATCH, 256>>>(x, gamma, beta);

    // main: GEMM1 first half (rows 0..1023) after cvt_wi
    cudaStreamWaitEvent(0, eCvtWi, 0);
    gemm_mma_kernel<<<dim3(2 * D_INNER / 128, HALF_B / 128), 128, GEMM_SMEM>>>(
        xh, wi, xz, nullptr, BATCH, 2 * D_INNER, D_MODEL, 0);
    cudaEventRecord(eG1a, 0);

    // main: GEMM1 second half
    gemm_mma_kernel<<<dim3(2 * D_INNER / 128, HALF_B / 128), 128, GEMM_SMEM>>>(
        xh, wi, xz, nullptr, BATCH, 2 * D_INNER, D_MODEL, HALF_B);
    cudaEventRecord(eG1b, 0);

    // s2 (overlapping GEMM1): W_out convert, expA, then half-A of xp+ssm
    cvt_kernel<<<(n4_wo + 255) / 256, 256, 0, s2>>>(W_out, wo, n4_wo);
    expA_kernel<<<(D_INNER * D_STATE + 255) / 256, 256, 0, s2>>>(log_A);
    cudaStreamWaitEvent(s2, eG1a, 0);
    xp_kernel<<<HALF_B / 16, 256, 0, s2>>>(W_xp, 0);
    ssm2_kernel<<<HALF_B * 64, 256, 0, s2>>>(h, dt_b, Dp, h_out, 0);
    cudaEventRecord(eSsmA, s2);

    // s2: half-B of xp+ssm after GEMM1b
    cudaStreamWaitEvent(s2, eG1b, 0);
    xp_kernel<<<HALF_B / 16, 256, 0, s2>>>(W_xp, HALF_B);
    ssm2_kernel<<<HALF_B * 64, 256, 0, s2>>>(h, dt_b, Dp, h_out, HALF_B);
    cudaEventRecord(eSsmB, s2);

    // main: GEMM2 halves (cvt_wo/expA ordered before eSsmA within s2)
    cudaStreamWaitEvent(0, eSsmA, 0);
    gemm_mma_kernel<<<dim3(D_MODEL / 128, HALF_B / 128), 128, GEMM_SMEM>>>(
        yg, wo, y_out, x, BATCH, D_MODEL, D_INNER, 0);
    cudaStreamWaitEvent(0, eSsmB, 0);
    gemm_mma_kernel<<<dim3(D_MODEL / 128, HALF_B / 128), 128, GEMM_SMEM>>>(
        yg, wo, y_out, x, BATCH, D_MODEL, D_INNER, HALF_B);
}